// round 3
// baseline (speedup 1.0000x reference)
#include <cuda_runtime.h>
#include <cuda_bf16.h>
#include <math.h>

// Problem constants
#define BB 2
#define TT 2048
#define DD 1024
#define HH 16
#define DKV 64
#define FFD 4096
#define BT (BB*TT)          // 4096

// ---------------- device scratch (no cudaMalloc allowed) ----------------
__device__ float g_wqkv[(size_t)DD * 3072];            // packed (D, 3*H*64)   12.6 MB
__device__ float g_qkv [(size_t)BT * 3072];            // Q|K|V per token      50 MB
__device__ float g_S   [(size_t)BB * HH * TT * TT];    // scores               512 MB
__device__ float g_O   [(size_t)BT * DD];              // attn out (B,T,H*DV)  16.8 MB
__device__ float g_out1[(size_t)BT * DD];              // after Wo+res+LN      16.8 MB
__device__ float g_h1  [(size_t)BT * FFD];             // FFN hidden           64 MB

// ---------------- weight repack: (H,D,64)x3 -> (D, 3072) ----------------
__global__ void repack_w_kernel(const float* __restrict__ Wq,
                                const float* __restrict__ Wk,
                                const float* __restrict__ Wv,
                                float* __restrict__ out) {
    int idx = blockIdx.x * blockDim.x + threadIdx.x;   // over D*3072
    if (idx >= DD * 3072) return;
    int d   = idx / 3072;
    int c   = idx % 3072;
    int sel = c >> 10;          // 0=Q 1=K 2=V
    int hc  = c & 1023;
    int h   = hc >> 6;
    int k   = hc & 63;
    const float* W = (sel == 0) ? Wq : (sel == 1) ? Wk : Wv;
    out[idx] = W[(size_t)h * DD * DKV + (size_t)d * DKV + k];
}

// ---------------- generic tiled SGEMM ----------------
// C[m][n] = alpha * sum_k A[m][k] * op(B)[k][n]  (+ epilogue)
// EPI: 0 none | 1 bias+relu | 2 bias+residual | 3 residual
// Batched over blockIdx.z with (b,h) decomposed strides.
template<int BM, int BN, int BK, int TM, int TN, bool TRANSB, int EPI>
__global__ __launch_bounds__((BM/TM)*(BN/TN))
void gemm_kernel(int M, int N, int K,
                 const float* __restrict__ A, int lda, long long sAb, long long sAh,
                 const float* __restrict__ B, int ldb, long long sBb, long long sBh,
                 float* __restrict__ C, int ldc, long long sCb, long long sCh,
                 const float* __restrict__ bias,
                 const float* __restrict__ Res, int ldr,
                 float alpha, int nheads)
{
    constexpr int NTHR = (BM/TM)*(BN/TN);
    const int tid = threadIdx.x;

    {
        int z = blockIdx.z;
        int b = z / nheads, h = z % nheads;
        A += (long long)b * sAb + (long long)h * sAh;
        B += (long long)b * sBb + (long long)h * sBh;
        C += (long long)b * sCb + (long long)h * sCh;
    }

    __shared__ float As[BK][BM];
    __shared__ float Bs[BK][BN];

    const int m0 = blockIdx.y * BM;
    const int n0 = blockIdx.x * BN;
    const int tx = tid % (BN/TN);
    const int ty = tid / (BN/TN);

    float acc[TM][TN];
#pragma unroll
    for (int i = 0; i < TM; i++)
#pragma unroll
        for (int j = 0; j < TN; j++) acc[i][j] = 0.f;

    constexpr int A_F4 = (BM*BK/4) / NTHR;   // per-thread float4 loads of A
    constexpr int B_F4 = (BK*BN/4) / NTHR;
    static_assert(A_F4 >= 1 && B_F4 >= 1, "tile config");

    for (int k0 = 0; k0 < K; k0 += BK) {
        // A tile -> As[k][m] (transposed in smem), float4 along k
#pragma unroll
        for (int t = 0; t < A_F4; t++) {
            int a  = tid + t * NTHR;
            int m  = a / (BK/4);
            int kq = (a % (BK/4)) * 4;
            float4 v = *reinterpret_cast<const float4*>(A + (long long)(m0 + m) * lda + k0 + kq);
            As[kq+0][m] = v.x; As[kq+1][m] = v.y; As[kq+2][m] = v.z; As[kq+3][m] = v.w;
        }
        if (!TRANSB) {
            // B[k][n], float4 along n
#pragma unroll
            for (int t = 0; t < B_F4; t++) {
                int bidx = tid + t * NTHR;
                int kk = bidx / (BN/4);
                int nq = (bidx % (BN/4)) * 4;
                *reinterpret_cast<float4*>(&Bs[kk][nq]) =
                    *reinterpret_cast<const float4*>(B + (long long)(k0 + kk) * ldb + n0 + nq);
            }
        } else {
            // B[n][k], float4 along k, scatter into Bs[k][n]
#pragma unroll
            for (int t = 0; t < B_F4; t++) {
                int bidx = tid + t * NTHR;
                int n  = bidx / (BK/4);
                int kq = (bidx % (BK/4)) * 4;
                float4 v = *reinterpret_cast<const float4*>(B + (long long)(n0 + n) * ldb + k0 + kq);
                Bs[kq+0][n] = v.x; Bs[kq+1][n] = v.y; Bs[kq+2][n] = v.z; Bs[kq+3][n] = v.w;
            }
        }
        __syncthreads();

#pragma unroll
        for (int kk = 0; kk < BK; kk++) {
            float af[TM], bf[TN];
#pragma unroll
            for (int i = 0; i < TM; i++) af[i] = As[kk][ty*TM + i];
#pragma unroll
            for (int j = 0; j < TN; j++) bf[j] = Bs[kk][tx*TN + j];
#pragma unroll
            for (int i = 0; i < TM; i++)
#pragma unroll
                for (int j = 0; j < TN; j++)
                    acc[i][j] = fmaf(af[i], bf[j], acc[i][j]);
        }
        __syncthreads();
    }

    // epilogue (all shapes multiples of tile — no bounds checks needed)
#pragma unroll
    for (int i = 0; i < TM; i++) {
        long long row = (long long)(m0 + ty*TM + i);
#pragma unroll
        for (int j = 0; j < TN; j += 4) {
            int n = n0 + tx*TN + j;
            float4 v;
            v.x = acc[i][j+0] * alpha;
            v.y = acc[i][j+1] * alpha;
            v.z = acc[i][j+2] * alpha;
            v.w = acc[i][j+3] * alpha;
            if (EPI == 1 || EPI == 2) {
                float4 bv = *reinterpret_cast<const float4*>(bias + n);
                v.x += bv.x; v.y += bv.y; v.z += bv.z; v.w += bv.w;
            }
            if (EPI == 2 || EPI == 3) {
                float4 rv = *reinterpret_cast<const float4*>(Res + row * ldr + n);
                v.x += rv.x; v.y += rv.y; v.z += rv.z; v.w += rv.w;
            }
            if (EPI == 1) {
                v.x = fmaxf(v.x, 0.f); v.y = fmaxf(v.y, 0.f);
                v.z = fmaxf(v.z, 0.f); v.w = fmaxf(v.w, 0.f);
            }
            *reinterpret_cast<float4*>(C + row * ldc + n) = v;
        }
    }
}

// ---------------- softmax over the QUERY axis (axis=-2) ----------------
// S layout per (b,h): [q][s] row-major, ld = T. Normalize each COLUMN s over q.
// Thread = one column; reads are coalesced across threads. In-place.
__global__ void softmax_q_kernel(float* __restrict__ S) {
    const int s = blockIdx.x * blockDim.x + threadIdx.x;        // column
    float* base = S + (long long)blockIdx.y * TT * TT;
    float m = -INFINITY, l = 0.f;
    for (int q = 0; q < TT; q++) {
        float v = base[(long long)q * TT + s];
        if (v > m) { l = l * __expf(m - v) + 1.f; m = v; }
        else       { l += __expf(v - m); }
    }
    float inv = 1.f / l;
    for (int q = 0; q < TT; q++) {
        long long idx = (long long)q * TT + s;
        base[idx] = __expf(base[idx] - m) * inv;
    }
}

// ---------------- mean/std norm (Bessel ddof=1), in place ----------------
__device__ __forceinline__ float block_reduce_sum_256(float v, float* red) {
#pragma unroll
    for (int o = 16; o > 0; o >>= 1) v += __shfl_xor_sync(0xffffffffu, v, o);
    int w = threadIdx.x >> 5;
    if ((threadIdx.x & 31) == 0) red[w] = v;
    __syncthreads();
    if (threadIdx.x < 8) {
        float t = red[threadIdx.x];
#pragma unroll
        for (int o = 4; o > 0; o >>= 1) t += __shfl_xor_sync(0xffu, t, o);
        if (threadIdx.x == 0) red[0] = t;
    }
    __syncthreads();
    float r = red[0];
    __syncthreads();
    return r;
}

__global__ __launch_bounds__(256) void ln_kernel(float* __restrict__ Y) {
    __shared__ float red[8];
    float4* y = reinterpret_cast<float4*>(Y + (long long)blockIdx.x * DD);
    float4 v = y[threadIdx.x];
    float s = block_reduce_sum_256(v.x + v.y + v.z + v.w, red);
    float mean = s * (1.f / DD);
    float dx = v.x - mean, dy = v.y - mean, dz = v.z - mean, dw = v.w - mean;
    float ss = block_reduce_sum_256(dx*dx + dy*dy + dz*dz + dw*dw, red);
    float rstd = rsqrtf(ss * (1.f / (DD - 1)));
    float4 o; o.x = dx*rstd; o.y = dy*rstd; o.z = dz*rstd; o.w = dw*rstd;
    y[threadIdx.x] = o;
}

// ---------------- launch ----------------
extern "C" void kernel_launch(void* const* d_in, const int* in_sizes, int n_in,
                              void* d_out, int out_size) {
    const float* x  = (const float*)d_in[0];
    const float* Wq = (const float*)d_in[1];
    const float* Wk = (const float*)d_in[2];
    const float* Wv = (const float*)d_in[3];
    const float* Wo = (const float*)d_in[4];
    const float* W1 = (const float*)d_in[5];
    const float* b1 = (const float*)d_in[6];
    const float* W2 = (const float*)d_in[7];
    const float* b2 = (const float*)d_in[8];
    float* out = (float*)d_out;

    float *wqkv, *qkv, *S, *O, *out1, *h1;
    cudaGetSymbolAddress((void**)&wqkv, g_wqkv);
    cudaGetSymbolAddress((void**)&qkv,  g_qkv);
    cudaGetSymbolAddress((void**)&S,    g_S);
    cudaGetSymbolAddress((void**)&O,    g_O);
    cudaGetSymbolAddress((void**)&out1, g_out1);
    cudaGetSymbolAddress((void**)&h1,   g_h1);

    // 0) repack QKV weights -> (D, 3072)
    repack_w_kernel<<<(DD*3072 + 255)/256, 256>>>(Wq, Wk, Wv, wqkv);

    // 1) QKV projection: (4096,1024) @ (1024,3072)
    gemm_kernel<128,128,8,8,8,false,0><<<dim3(3072/128, BT/128, 1), 256>>>(
        BT, 3072, DD,
        x,    DD,   0, 0,
        wqkv, 3072, 0, 0,
        qkv,  3072, 0, 0,
        nullptr, nullptr, 0, 1.f, 1);

    // 2) scores = Q @ K^T / 8  per (b,h): NT GEMM, M=N=2048, K=64
    gemm_kernel<128,128,8,8,8,true,0><<<dim3(TT/128, TT/128, BB*HH), 256>>>(
        TT, TT, DKV,
        qkv,        3072, (long long)TT*3072, DKV,
        qkv + 1024, 3072, (long long)TT*3072, DKV,
        S,          TT,   (long long)HH*TT*TT, (long long)TT*TT,
        nullptr, nullptr, 0, 0.125f, HH);

    // 3) softmax over query axis (columns of S)
    softmax_q_kernel<<<dim3(TT/256, BB*HH), 256>>>(S);

    // 4) O = attn @ V  per (b,h): M=2048, N=64, K=2048
    gemm_kernel<128,64,16,8,4,false,0><<<dim3(1, TT/128, BB*HH), 256>>>(
        TT, DKV, TT,
        S,          TT,   (long long)HH*TT*TT, (long long)TT*TT,
        qkv + 2048, 3072, (long long)TT*3072, DKV,
        O,          DD,   (long long)TT*DD,   DKV,
        nullptr, nullptr, 0, 1.f, HH);

    // 5) out1 = LN(O @ Wo + x)
    gemm_kernel<128,128,8,8,8,false,3><<<dim3(DD/128, BT/128, 1), 256>>>(
        BT, DD, DD,
        O,  DD, 0, 0,
        Wo, DD, 0, 0,
        out1, DD, 0, 0,
        nullptr, x, DD, 1.f, 1);
    ln_kernel<<<BT, 256>>>(out1);

    // 6) h1 = relu(out1 @ W1 + b1)
    gemm_kernel<128,128,8,8,8,false,1><<<dim3(FFD/128, BT/128, 1), 256>>>(
        BT, FFD, DD,
        out1, DD,  0, 0,
        W1,   FFD, 0, 0,
        h1,   FFD, 0, 0,
        b1, nullptr, 0, 1.f, 1);

    // 7) out = LN(h1 @ W2 + b2 + out1)
    gemm_kernel<128,128,8,8,8,false,2><<<dim3(DD/128, BT/128, 1), 256>>>(
        BT, DD, FFD,
        h1, FFD, 0, 0,
        W2, DD,  0, 0,
        out, DD, 0, 0,
        b2, out1, DD, 1.f, 1);
    ln_kernel<<<BT, 256>>>(out);
}